// round 15
// baseline (speedup 1.0000x reference)
#include <cuda_runtime.h>
#include <cuda_fp16.h>
#include <cstdint>

// ---------------------------------------------------------------------------
// Round 15: R13 GEMM (batched QKV grid.z=3, 64x64 warp tiles, ping-pong frags,
//           3-stage cp.async, oversubscribed grid) + shfl-segment softmax
//           attn_ln from R14. Work-stealing reverted (pipeline-drain loss).
// ---------------------------------------------------------------------------

#define M_TOK   16384
#define DMODEL  1024
#define NTOK_EL (M_TOK * DMODEL)
#define NW_EL   (DMODEL * DMODEL)

__device__ __half g_aq[NTOK_EL];
__device__ __half g_ak[NTOK_EL];
__device__ __half g_av[NTOK_EL];
__device__ __half g_q16[NTOK_EL];
__device__ __half g_k16[NTOK_EL];
__device__ __half g_v16[NTOK_EL];
__device__ __half g_x16[NTOK_EL];
__device__ __half g_wq[NW_EL];
__device__ __half g_wk[NW_EL];
__device__ __half g_wv[NW_EL];
__device__ __half g_wo[NW_EL];

// ---------------- PTX helpers ----------------
__device__ __forceinline__ uint32_t smem_u32(const void* p) {
    return (uint32_t)__cvta_generic_to_shared(p);
}
__device__ __forceinline__ void cp16(uint32_t dst, const void* src) {
    asm volatile("cp.async.cg.shared.global [%0], [%1], 16;"
                 :: "r"(dst), "l"(src) : "memory");
}
__device__ __forceinline__ void cp_commit() {
    asm volatile("cp.async.commit_group;" ::: "memory");
}
__device__ __forceinline__ void cp_wait1() {
    asm volatile("cp.async.wait_group 1;" ::: "memory");
}
__device__ __forceinline__ void ldsm4(uint32_t* r, uint32_t addr) {
    asm volatile("ldmatrix.sync.aligned.m8n8.x4.shared.b16 {%0,%1,%2,%3}, [%4];"
                 : "=r"(r[0]), "=r"(r[1]), "=r"(r[2]), "=r"(r[3]) : "r"(addr));
}
__device__ __forceinline__ void mma16816(float* c, const uint32_t* a, const uint32_t* b) {
    asm volatile(
        "mma.sync.aligned.m16n8k16.row.col.f32.f16.f16.f32 "
        "{%0,%1,%2,%3}, {%4,%5,%6,%7}, {%8,%9}, {%0,%1,%2,%3};"
        : "+f"(c[0]), "+f"(c[1]), "+f"(c[2]), "+f"(c[3])
        : "r"(a[0]), "r"(a[1]), "r"(a[2]), "r"(a[3]), "r"(b[0]), "r"(b[1]));
}

// ---------------- fused convert: 3 activations + 4 weights ----------------
#define ACT_BLKS 8192
#define W_BLKS   512

__global__ __launch_bounds__(256)
void conv_all(const float* __restrict__ a0, const float* __restrict__ a1,
              const float* __restrict__ a2,
              const float* __restrict__ w0, const float* __restrict__ w1,
              const float* __restrict__ w2, const float* __restrict__ w3,
              __half* __restrict__ ya0, __half* __restrict__ ya1,
              __half* __restrict__ ya2,
              __half* __restrict__ yw0, __half* __restrict__ yw1,
              __half* __restrict__ yw2, __half* __restrict__ yw3)
{
    int b = blockIdx.x;
    const float* x; __half* y; int blk;
    if (b < 3 * ACT_BLKS) {
        int t = b / ACT_BLKS;
        x = (t == 0) ? a0 : (t == 1) ? a1 : a2;
        y = (t == 0) ? ya0 : (t == 1) ? ya1 : ya2;
        blk = b - t * ACT_BLKS;
    } else {
        int r = b - 3 * ACT_BLKS;
        int t = r / W_BLKS;
        x = (t == 0) ? w0 : (t == 1) ? w1 : (t == 2) ? w2 : w3;
        y = (t == 0) ? yw0 : (t == 1) ? yw1 : (t == 2) ? yw2 : yw3;
        blk = r - t * W_BLKS;
    }
    int i = (blk * 256 + threadIdx.x) * 8;
    float4 v0 = *(const float4*)(x + i);
    float4 v1 = *(const float4*)(x + i + 4);
    __half2 h[4];
    h[0] = __floats2half2_rn(v0.x, v0.y);
    h[1] = __floats2half2_rn(v0.z, v0.w);
    h[2] = __floats2half2_rn(v1.x, v1.y);
    h[3] = __floats2half2_rn(v1.z, v1.w);
    *(uint4*)(y + i) = *(uint4*)h;
}

// ---------------- HMMA GEMM core: CTA 128x128, warp 64x64, BK=64 ----------
#define BK          64
#define MAT_BYTES   16384         // 128 rows * 128B
#define STAGE_BYTES 32768         // A | W
#define STAGES      3
#define GEMM_SMEM   (STAGES * STAGE_BYTES)

__device__ __forceinline__ void load_stage(const __half* A, const __half* W,
                                           int kb, uint32_t sdst,
                                           int tid, int m0, int n0, int K)
{
    #pragma unroll
    for (int i = 0; i < 16; i++) {
        const int id  = i * 128 + tid;
        const int mat = id >> 10;               // 0:A 1:W
        const int idx = id & 1023;
        const int row = idx >> 3;
        const int ch  = idx & 7;
        const int grow = ((mat == 0) ? m0 : n0) + row;
        const __half* src = (mat == 0) ? A : W;
        const void* g = src + (size_t)grow * K + kb * BK + ch * 8;
        const uint32_t d = sdst + mat * MAT_BYTES + row * 128
                         + (((uint32_t)(ch ^ (row & 7))) << 4);
        cp16(d, g);
    }
}

template <typename OutT>
__device__ __forceinline__ void gemm_core(const __half* A, const __half* W,
                                          const float* bias, OutT* C,
                                          int K, int Ntot, int m0, int n0,
                                          char* smem)
{
    const uint32_t sbase = smem_u32(smem);
    const int tid  = threadIdx.x;
    const int lane = tid & 31;
    const int wid  = tid >> 5;
    const int wm   = wid >> 1;
    const int wn   = wid & 1;

    const int g = lane >> 3, j = lane & 7;
    const int cA = g >> 1;
    const int rowA_base = wm * 64 + ((g & 1) ? 8 : 0) + j;
    const int cB = g & 1;
    const int rowB_base = wn * 64 + ((g >> 1) ? 8 : 0) + j;

    float acc[4][8][4];
    #pragma unroll
    for (int a = 0; a < 4; a++)
        #pragma unroll
        for (int b = 0; b < 8; b++)
            #pragma unroll
            for (int c = 0; c < 4; c++) acc[a][b][c] = 0.f;

    uint32_t ar[2][4][4];
    uint32_t bw[2][16];

    auto load_frags = [&](int buf, int k16, uint32_t st) {
        const int c0 = k16 * 2;
        #pragma unroll
        for (int mf = 0; mf < 4; mf++) {
            const int row = rowA_base + mf * 16;
            const uint32_t ad = st + row * 128
                + (((uint32_t)((c0 + cA) ^ (row & 7))) << 4);
            ldsm4(ar[buf][mf], ad);
        }
        #pragma unroll
        for (int p = 0; p < 4; p++) {
            const int row = rowB_base + p * 16;
            const uint32_t bd = st + MAT_BYTES + row * 128
                + (((uint32_t)((c0 + cB) ^ (row & 7))) << 4);
            ldsm4(&bw[buf][p * 4], bd);
        }
    };

    const int nkb = K / BK;       // 16
    load_stage(A, W, 0, sbase,               tid, m0, n0, K); cp_commit();
    load_stage(A, W, 1, sbase + STAGE_BYTES, tid, m0, n0, K); cp_commit();

    for (int kb = 0; kb < nkb; kb++) {
        cp_wait1();
        __syncthreads();
        if (kb + 2 < nkb)
            load_stage(A, W, kb + 2, sbase + ((kb + 2) % STAGES) * STAGE_BYTES,
                       tid, m0, n0, K);
        cp_commit();

        const uint32_t st = sbase + (kb % STAGES) * STAGE_BYTES;
        load_frags(0, 0, st);

        #pragma unroll
        for (int k16 = 0; k16 < 4; k16++) {
            const int cur = k16 & 1;
            if (k16 < 3) load_frags(cur ^ 1, k16 + 1, st);
            #pragma unroll
            for (int mf = 0; mf < 4; mf++)
                #pragma unroll
                for (int nf = 0; nf < 8; nf++)
                    mma16816(acc[mf][nf], ar[cur][mf], &bw[cur][nf * 2]);
        }
    }

    // epilogue
    const int rl = lane >> 2;
    const int cl = (lane & 3) * 2;
    #pragma unroll
    for (int mf = 0; mf < 4; mf++) {
        const int grow = m0 + wm * 64 + mf * 16 + rl;
        #pragma unroll
        for (int nf = 0; nf < 8; nf++) {
            const int gcol = n0 + wn * 64 + nf * 8 + cl;
            const float2 b2 = *(const float2*)&bias[gcol];
            float v0 = acc[mf][nf][0] + b2.x, v1 = acc[mf][nf][1] + b2.y;
            float v2 = acc[mf][nf][2] + b2.x, v3 = acc[mf][nf][3] + b2.y;
            if constexpr (sizeof(OutT) == 4) {
                *(float2*)&C[(size_t)grow * Ntot + gcol]       = make_float2(v0, v1);
                *(float2*)&C[(size_t)(grow + 8) * Ntot + gcol] = make_float2(v2, v3);
            } else {
                *(__half2*)&C[(size_t)grow * Ntot + gcol]       = __floats2half2_rn(v0, v1);
                *(__half2*)&C[(size_t)(grow + 8) * Ntot + gcol] = __floats2half2_rn(v2, v3);
            }
        }
    }
}

template <typename OutT>
__global__ __launch_bounds__(128, 2)
void gemm_mma(const __half* __restrict__ A, const __half* __restrict__ W,
              const float* __restrict__ bias, OutT* __restrict__ C,
              int K, int Ntot)
{
    extern __shared__ char smem[];
    gemm_core<OutT>(A, W, bias, C, K, Ntot,
                    blockIdx.y * 128, blockIdx.x * 128, smem);
}

struct QKVArgs {
    const __half* A[3];
    const __half* W[3];
    const float*  bias[3];
    __half*       C[3];
};

__global__ __launch_bounds__(128, 2)
void gemm_qkv(QKVArgs args, int K, int Ntot)
{
    extern __shared__ char smem[];
    const int z = blockIdx.z;
    gemm_core<__half>(args.A[z], args.W[z], args.bias[z], args.C[z], K, Ntot,
                      blockIdx.y * 128, blockIdx.x * 128, smem);
}

// ---------------- per-token head-mix attention + LayerNorm -----------------
// shfl-segment softmax: thread (h = tid>>4, g = tid&15); 16-lane segments.
__global__ __launch_bounds__(256)
void attn_ln(const __half* __restrict__ Q, const __half* __restrict__ Kp,
             const __half* __restrict__ V, const float* __restrict__ lng,
             const float* __restrict__ lnb, __half* __restrict__ X)
{
    __shared__ float4 sq4[256];
    __shared__ float4 sv4[256];
    __shared__ float4 sk4[16 * 17];
    __shared__ float  rbuf[2][8];

    const int tid = threadIdx.x;
    const size_t base = (size_t)blockIdx.x * 1024;
    const int h  = tid >> 4;
    const int d4 = tid & 15;

    auto ld4h = [&](const __half* p) -> float4 {
        uint2 u = *(const uint2*)(p + base + tid * 4);
        float2 a = __half22float2(*(__half2*)&u.x);
        float2 b = __half22float2(*(__half2*)&u.y);
        return make_float4(a.x, a.y, b.x, b.y);
    };
    sq4[tid] = ld4h(Q);
    sv4[tid] = ld4h(V);
    sk4[h * 17 + d4] = ld4h(Kp);
    __syncthreads();

    // energy for (h, g=d4)
    float e = 0.f;
    {
        const int gg = d4;
        #pragma unroll
        for (int q4i = 0; q4i < 16; q4i++) {
            float4 a = sq4[h * 16 + q4i];
            float4 b = sk4[gg * 17 + q4i];
            e += a.x * b.x + a.y * b.y + a.z * b.z + a.w * b.w;
        }
        e *= 0.03125f;   // 1/sqrt(1024)
    }

    // softmax over g within the 16-lane segment
    float mx = e;
    #pragma unroll
    for (int off = 8; off > 0; off >>= 1)
        mx = fmaxf(mx, __shfl_xor_sync(0xffffffffu, mx, off, 16));
    float p = __expf(e - mx);
    float s = p;
    #pragma unroll
    for (int off = 8; off > 0; off >>= 1)
        s += __shfl_xor_sync(0xffffffffu, s, off, 16);
    const float attn = p / s;

    // head mix: out[h, d4*4 .. d4*4+3]; attn[h][gg] via segment broadcast
    float4 o = make_float4(0.f, 0.f, 0.f, 0.f);
    #pragma unroll
    for (int gg = 0; gg < 16; gg++) {
        const float w = __shfl_sync(0xffffffffu, attn, gg, 16);
        const float4 vv = sv4[gg * 16 + d4];
        o.x += w * vv.x; o.y += w * vv.y; o.z += w * vv.z; o.w += w * vv.w;
    }
    float s1 = o.x + o.y + o.z + o.w;
    float s2 = o.x * o.x + o.y * o.y + o.z * o.z + o.w * o.w;

    #pragma unroll
    for (int off = 16; off > 0; off >>= 1) {
        s1 += __shfl_xor_sync(0xffffffffu, s1, off);
        s2 += __shfl_xor_sync(0xffffffffu, s2, off);
    }
    const int wid = tid >> 5, lane = tid & 31;
    if (lane == 0) { rbuf[0][wid] = s1; rbuf[1][wid] = s2; }
    __syncthreads();
    if (tid == 0) {
        float t1 = 0.f, t2 = 0.f;
        #pragma unroll
        for (int w = 0; w < 8; w++) { t1 += rbuf[0][w]; t2 += rbuf[1][w]; }
        float mu  = t1 * (1.f / 1024.f);
        float var = t2 * (1.f / 1024.f) - mu * mu;
        rbuf[0][0] = mu;
        rbuf[1][0] = rsqrtf(var + 1e-5f);
    }
    __syncthreads();
    const float mu = rbuf[0][0], rstd = rbuf[1][0];

    const float4 gam = *(const float4*)&lng[tid * 4];
    const float4 bet = *(const float4*)&lnb[tid * 4];
    float4 r;
    r.x = (o.x - mu) * rstd * gam.x + bet.x;
    r.y = (o.y - mu) * rstd * gam.y + bet.y;
    r.z = (o.z - mu) * rstd * gam.z + bet.z;
    r.w = (o.w - mu) * rstd * gam.w + bet.w;
    __half2 h01 = __floats2half2_rn(r.x, r.y);
    __half2 h23 = __floats2half2_rn(r.z, r.w);
    uint2 pk;
    pk.x = *(uint32_t*)&h01;
    pk.y = *(uint32_t*)&h23;
    *(uint2*)&X[base + tid * 4] = pk;
}

// ---------------- launch ----------------
extern "C" void kernel_launch(void* const* d_in, const int* in_sizes, int n_in,
                              void* d_out, int out_size)
{
    const float* query = (const float*)d_in[0];
    const float* key   = (const float*)d_in[1];
    const float* value = (const float*)d_in[2];
    const float* Wq    = (const float*)d_in[3];
    const float* bq    = (const float*)d_in[4];
    const float* Wk    = (const float*)d_in[5];
    const float* bk    = (const float*)d_in[6];
    const float* Wv    = (const float*)d_in[7];
    const float* bv    = (const float*)d_in[8];
    const float* lng   = (const float*)d_in[9];
    const float* lnb   = (const float*)d_in[10];
    const float* Wo    = (const float*)d_in[11];
    const float* bo    = (const float*)d_in[12];
    float* out = (float*)d_out;

    __half *paq, *pak, *pav, *pq, *pk, *pv, *px;
    __half *pwq, *pwk, *pwv, *pwo;
    cudaGetSymbolAddress((void**)&paq, g_aq);
    cudaGetSymbolAddress((void**)&pak, g_ak);
    cudaGetSymbolAddress((void**)&pav, g_av);
    cudaGetSymbolAddress((void**)&pq,  g_q16);
    cudaGetSymbolAddress((void**)&pk,  g_k16);
    cudaGetSymbolAddress((void**)&pv,  g_v16);
    cudaGetSymbolAddress((void**)&px,  g_x16);
    cudaGetSymbolAddress((void**)&pwq, g_wq);
    cudaGetSymbolAddress((void**)&pwk, g_wk);
    cudaGetSymbolAddress((void**)&pwv, g_wv);
    cudaGetSymbolAddress((void**)&pwo, g_wo);

    cudaFuncSetAttribute(gemm_mma<float>,
                         cudaFuncAttributeMaxDynamicSharedMemorySize, GEMM_SMEM);
    cudaFuncSetAttribute(gemm_qkv,
                         cudaFuncAttributeMaxDynamicSharedMemorySize, GEMM_SMEM);

    conv_all<<<3 * ACT_BLKS + 4 * W_BLKS, 256>>>(
        query, key, value, Wq, Wk, Wv, Wo,
        paq, pak, pav, pwq, pwk, pwv, pwo);

    QKVArgs args;
    args.A[0] = paq; args.A[1] = pak; args.A[2] = pav;
    args.W[0] = pwq; args.W[1] = pwk; args.W[2] = pwv;
    args.bias[0] = bq; args.bias[1] = bk; args.bias[2] = bv;
    args.C[0] = pq; args.C[1] = pk; args.C[2] = pv;
    dim3 gq(DMODEL / 128, M_TOK / 128, 3);
    gemm_qkv<<<gq, 128, GEMM_SMEM>>>(args, DMODEL, DMODEL);

    attn_ln<<<M_TOK, 256>>>(pq, pk, pv, lng, lnb, px);

    dim3 gg(DMODEL / 128, M_TOK / 128);
    gemm_mma<float><<<gg, 128, GEMM_SMEM>>>(px, pwo, bo, out, DMODEL, DMODEL);
}

// round 16
// speedup vs baseline: 1.5059x; 1.5059x over previous
#include <cuda_runtime.h>
#include <cuda_fp16.h>
#include <cstdint>

// ---------------------------------------------------------------------------
// Round 16: re-bench of R15 config (R13 GEMM + shfl-segment attn_ln).
// R15's 753us showed uniform ~1.51x scaling with unchanged pipe% on an
// unchanged kernel => clock-throttled run, not a code regression. A/B re-run.
// ---------------------------------------------------------------------------

#define M_TOK   16384
#define DMODEL  1024
#define NTOK_EL (M_TOK * DMODEL)
#define NW_EL   (DMODEL * DMODEL)

__device__ __half g_aq[NTOK_EL];
__device__ __half g_ak[NTOK_EL];
__device__ __half g_av[NTOK_EL];
__device__ __half g_q16[NTOK_EL];
__device__ __half g_k16[NTOK_EL];
__device__ __half g_v16[NTOK_EL];
__device__ __half g_x16[NTOK_EL];
__device__ __half g_wq[NW_EL];
__device__ __half g_wk[NW_EL];
__device__ __half g_wv[NW_EL];
__device__ __half g_wo[NW_EL];

// ---------------- PTX helpers ----------------
__device__ __forceinline__ uint32_t smem_u32(const void* p) {
    return (uint32_t)__cvta_generic_to_shared(p);
}
__device__ __forceinline__ void cp16(uint32_t dst, const void* src) {
    asm volatile("cp.async.cg.shared.global [%0], [%1], 16;"
                 :: "r"(dst), "l"(src) : "memory");
}
__device__ __forceinline__ void cp_commit() {
    asm volatile("cp.async.commit_group;" ::: "memory");
}
__device__ __forceinline__ void cp_wait1() {
    asm volatile("cp.async.wait_group 1;" ::: "memory");
}
__device__ __forceinline__ void ldsm4(uint32_t* r, uint32_t addr) {
    asm volatile("ldmatrix.sync.aligned.m8n8.x4.shared.b16 {%0,%1,%2,%3}, [%4];"
                 : "=r"(r[0]), "=r"(r[1]), "=r"(r[2]), "=r"(r[3]) : "r"(addr));
}
__device__ __forceinline__ void mma16816(float* c, const uint32_t* a, const uint32_t* b) {
    asm volatile(
        "mma.sync.aligned.m16n8k16.row.col.f32.f16.f16.f32 "
        "{%0,%1,%2,%3}, {%4,%5,%6,%7}, {%8,%9}, {%0,%1,%2,%3};"
        : "+f"(c[0]), "+f"(c[1]), "+f"(c[2]), "+f"(c[3])
        : "r"(a[0]), "r"(a[1]), "r"(a[2]), "r"(a[3]), "r"(b[0]), "r"(b[1]));
}

// ---------------- fused convert: 3 activations + 4 weights ----------------
#define ACT_BLKS 8192
#define W_BLKS   512

__global__ __launch_bounds__(256)
void conv_all(const float* __restrict__ a0, const float* __restrict__ a1,
              const float* __restrict__ a2,
              const float* __restrict__ w0, const float* __restrict__ w1,
              const float* __restrict__ w2, const float* __restrict__ w3,
              __half* __restrict__ ya0, __half* __restrict__ ya1,
              __half* __restrict__ ya2,
              __half* __restrict__ yw0, __half* __restrict__ yw1,
              __half* __restrict__ yw2, __half* __restrict__ yw3)
{
    int b = blockIdx.x;
    const float* x; __half* y; int blk;
    if (b < 3 * ACT_BLKS) {
        int t = b / ACT_BLKS;
        x = (t == 0) ? a0 : (t == 1) ? a1 : a2;
        y = (t == 0) ? ya0 : (t == 1) ? ya1 : ya2;
        blk = b - t * ACT_BLKS;
    } else {
        int r = b - 3 * ACT_BLKS;
        int t = r / W_BLKS;
        x = (t == 0) ? w0 : (t == 1) ? w1 : (t == 2) ? w2 : w3;
        y = (t == 0) ? yw0 : (t == 1) ? yw1 : (t == 2) ? yw2 : yw3;
        blk = r - t * W_BLKS;
    }
    int i = (blk * 256 + threadIdx.x) * 8;
    float4 v0 = *(const float4*)(x + i);
    float4 v1 = *(const float4*)(x + i + 4);
    __half2 h[4];
    h[0] = __floats2half2_rn(v0.x, v0.y);
    h[1] = __floats2half2_rn(v0.z, v0.w);
    h[2] = __floats2half2_rn(v1.x, v1.y);
    h[3] = __floats2half2_rn(v1.z, v1.w);
    *(uint4*)(y + i) = *(uint4*)h;
}

// ---------------- HMMA GEMM core: CTA 128x128, warp 64x64, BK=64 ----------
#define BK          64
#define MAT_BYTES   16384         // 128 rows * 128B
#define STAGE_BYTES 32768         // A | W
#define STAGES      3
#define GEMM_SMEM   (STAGES * STAGE_BYTES)

__device__ __forceinline__ void load_stage(const __half* A, const __half* W,
                                           int kb, uint32_t sdst,
                                           int tid, int m0, int n0, int K)
{
    #pragma unroll
    for (int i = 0; i < 16; i++) {
        const int id  = i * 128 + tid;
        const int mat = id >> 10;               // 0:A 1:W
        const int idx = id & 1023;
        const int row = idx >> 3;
        const int ch  = idx & 7;
        const int grow = ((mat == 0) ? m0 : n0) + row;
        const __half* src = (mat == 0) ? A : W;
        const void* g = src + (size_t)grow * K + kb * BK + ch * 8;
        const uint32_t d = sdst + mat * MAT_BYTES + row * 128
                         + (((uint32_t)(ch ^ (row & 7))) << 4);
        cp16(d, g);
    }
}

template <typename OutT>
__device__ __forceinline__ void gemm_core(const __half* A, const __half* W,
                                          const float* bias, OutT* C,
                                          int K, int Ntot, int m0, int n0,
                                          char* smem)
{
    const uint32_t sbase = smem_u32(smem);
    const int tid  = threadIdx.x;
    const int lane = tid & 31;
    const int wid  = tid >> 5;
    const int wm   = wid >> 1;
    const int wn   = wid & 1;

    const int g = lane >> 3, j = lane & 7;
    const int cA = g >> 1;
    const int rowA_base = wm * 64 + ((g & 1) ? 8 : 0) + j;
    const int cB = g & 1;
    const int rowB_base = wn * 64 + ((g >> 1) ? 8 : 0) + j;

    float acc[4][8][4];
    #pragma unroll
    for (int a = 0; a < 4; a++)
        #pragma unroll
        for (int b = 0; b < 8; b++)
            #pragma unroll
            for (int c = 0; c < 4; c++) acc[a][b][c] = 0.f;

    uint32_t ar[2][4][4];
    uint32_t bw[2][16];

    auto load_frags = [&](int buf, int k16, uint32_t st) {
        const int c0 = k16 * 2;
        #pragma unroll
        for (int mf = 0; mf < 4; mf++) {
            const int row = rowA_base + mf * 16;
            const uint32_t ad = st + row * 128
                + (((uint32_t)((c0 + cA) ^ (row & 7))) << 4);
            ldsm4(ar[buf][mf], ad);
        }
        #pragma unroll
        for (int p = 0; p < 4; p++) {
            const int row = rowB_base + p * 16;
            const uint32_t bd = st + MAT_BYTES + row * 128
                + (((uint32_t)((c0 + cB) ^ (row & 7))) << 4);
            ldsm4(&bw[buf][p * 4], bd);
        }
    };

    const int nkb = K / BK;       // 16
    load_stage(A, W, 0, sbase,               tid, m0, n0, K); cp_commit();
    load_stage(A, W, 1, sbase + STAGE_BYTES, tid, m0, n0, K); cp_commit();

    for (int kb = 0; kb < nkb; kb++) {
        cp_wait1();
        __syncthreads();
        if (kb + 2 < nkb)
            load_stage(A, W, kb + 2, sbase + ((kb + 2) % STAGES) * STAGE_BYTES,
                       tid, m0, n0, K);
        cp_commit();

        const uint32_t st = sbase + (kb % STAGES) * STAGE_BYTES;
        load_frags(0, 0, st);

        #pragma unroll
        for (int k16 = 0; k16 < 4; k16++) {
            const int cur = k16 & 1;
            if (k16 < 3) load_frags(cur ^ 1, k16 + 1, st);
            #pragma unroll
            for (int mf = 0; mf < 4; mf++)
                #pragma unroll
                for (int nf = 0; nf < 8; nf++)
                    mma16816(acc[mf][nf], ar[cur][mf], &bw[cur][nf * 2]);
        }
    }

    // epilogue
    const int rl = lane >> 2;
    const int cl = (lane & 3) * 2;
    #pragma unroll
    for (int mf = 0; mf < 4; mf++) {
        const int grow = m0 + wm * 64 + mf * 16 + rl;
        #pragma unroll
        for (int nf = 0; nf < 8; nf++) {
            const int gcol = n0 + wn * 64 + nf * 8 + cl;
            const float2 b2 = __ldg((const float2*)&bias[gcol]);
            float v0 = acc[mf][nf][0] + b2.x, v1 = acc[mf][nf][1] + b2.y;
            float v2 = acc[mf][nf][2] + b2.x, v3 = acc[mf][nf][3] + b2.y;
            if constexpr (sizeof(OutT) == 4) {
                *(float2*)&C[(size_t)grow * Ntot + gcol]       = make_float2(v0, v1);
                *(float2*)&C[(size_t)(grow + 8) * Ntot + gcol] = make_float2(v2, v3);
            } else {
                *(__half2*)&C[(size_t)grow * Ntot + gcol]       = __floats2half2_rn(v0, v1);
                *(__half2*)&C[(size_t)(grow + 8) * Ntot + gcol] = __floats2half2_rn(v2, v3);
            }
        }
    }
}

template <typename OutT>
__global__ __launch_bounds__(128, 2)
void gemm_mma(const __half* __restrict__ A, const __half* __restrict__ W,
              const float* __restrict__ bias, OutT* __restrict__ C,
              int K, int Ntot)
{
    extern __shared__ char smem[];
    gemm_core<OutT>(A, W, bias, C, K, Ntot,
                    blockIdx.y * 128, blockIdx.x * 128, smem);
}

struct QKVArgs {
    const __half* A[3];
    const __half* W[3];
    const float*  bias[3];
    __half*       C[3];
};

__global__ __launch_bounds__(128, 2)
void gemm_qkv(QKVArgs args, int K, int Ntot)
{
    extern __shared__ char smem[];
    const int z = blockIdx.z;
    gemm_core<__half>(args.A[z], args.W[z], args.bias[z], args.C[z], K, Ntot,
                      blockIdx.y * 128, blockIdx.x * 128, smem);
}

// ---------------- per-token head-mix attention + LayerNorm -----------------
__global__ __launch_bounds__(256)
void attn_ln(const __half* __restrict__ Q, const __half* __restrict__ Kp,
             const __half* __restrict__ V, const float* __restrict__ lng,
             const float* __restrict__ lnb, __half* __restrict__ X)
{
    __shared__ float4 sq4[256];
    __shared__ float4 sv4[256];
    __shared__ float4 sk4[16 * 17];
    __shared__ float  rbuf[2][8];

    const int tid = threadIdx.x;
    const size_t base = (size_t)blockIdx.x * 1024;
    const int h  = tid >> 4;
    const int d4 = tid & 15;

    auto ld4h = [&](const __half* p) -> float4 {
        uint2 u = *(const uint2*)(p + base + tid * 4);
        float2 a = __half22float2(*(__half2*)&u.x);
        float2 b = __half22float2(*(__half2*)&u.y);
        return make_float4(a.x, a.y, b.x, b.y);
    };
    sq4[tid] = ld4h(Q);
    sv4[tid] = ld4h(V);
    sk4[h * 17 + d4] = ld4h(Kp);
    __syncthreads();

    float e = 0.f;
    {
        const int gg = d4;
        #pragma unroll
        for (int q4i = 0; q4i < 16; q4i++) {
            float4 a = sq4[h * 16 + q4i];
            float4 b = sk4[gg * 17 + q4i];
            e += a.x * b.x + a.y * b.y + a.z * b.z + a.w * b.w;
        }
        e *= 0.03125f;   // 1/sqrt(1024)
    }

    float mx = e;
    #pragma unroll
    for (int off = 8; off > 0; off >>= 1)
        mx = fmaxf(mx, __shfl_xor_sync(0xffffffffu, mx, off, 16));
    float p = __expf(e - mx);
    float s = p;
    #pragma unroll
    for (int off = 8; off > 0; off >>= 1)
        s += __shfl_xor_sync(0xffffffffu, s, off, 16);
    const float attn = p / s;

    float4 o = make_float4(0.f, 0.f, 0.f, 0.f);
    #pragma unroll
    for (int gg = 0; gg < 16; gg++) {
        const float w = __shfl_sync(0xffffffffu, attn, gg, 16);
        const float4 vv = sv4[gg * 16 + d4];
        o.x += w * vv.x; o.y += w * vv.y; o.z += w * vv.z; o.w += w * vv.w;
    }
    float s1 = o.x + o.y + o.z + o.w;
    float s2 = o.x * o.x + o.y * o.y + o.z * o.z + o.w * o.w;

    #pragma unroll
    for (int off = 16; off > 0; off >>= 1) {
        s1 += __shfl_xor_sync(0xffffffffu, s1, off);
        s2 += __shfl_xor_sync(0xffffffffu, s2, off);
    }
    const int wid = tid >> 5, lane = tid & 31;
    if (lane == 0) { rbuf[0][wid] = s1; rbuf[1][wid] = s2; }
    __syncthreads();
    if (tid == 0) {
        float t1 = 0.f, t2 = 0.f;
        #pragma unroll
        for (int w = 0; w < 8; w++) { t1 += rbuf[0][w]; t2 += rbuf[1][w]; }
        float mu  = t1 * (1.f / 1024.f);
        float var = t2 * (1.f / 1024.f) - mu * mu;
        rbuf[0][0] = mu;
        rbuf[1][0] = rsqrtf(var + 1e-5f);
    }
    __syncthreads();
    const float mu = rbuf[0][0], rstd = rbuf[1][0];

    const float4 gam = *(const float4*)&lng[tid * 4];
    const float4 bet = *(const float4*)&lnb[tid * 4];
    float4 r;
    r.x = (o.x - mu) * rstd * gam.x + bet.x;
    r.y = (o.y - mu) * rstd * gam.y + bet.y;
    r.z = (o.z - mu) * rstd * gam.z + bet.z;
    r.w = (o.w - mu) * rstd * gam.w + bet.w;
    __half2 h01 = __floats2half2_rn(r.x, r.y);
    __half2 h23 = __floats2half2_rn(r.z, r.w);
    uint2 pk;
    pk.x = *(uint32_t*)&h01;
    pk.y = *(uint32_t*)&h23;
    *(uint2*)&X[base + tid * 4] = pk;
}

// ---------------- launch ----------------
extern "C" void kernel_launch(void* const* d_in, const int* in_sizes, int n_in,
                              void* d_out, int out_size)
{
    const float* query = (const float*)d_in[0];
    const float* key   = (const float*)d_in[1];
    const float* value = (const float*)d_in[2];
    const float* Wq    = (const float*)d_in[3];
    const float* bq    = (const float*)d_in[4];
    const float* Wk    = (const float*)d_in[5];
    const float* bk    = (const float*)d_in[6];
    const float* Wv    = (const float*)d_in[7];
    const float* bv    = (const float*)d_in[8];
    const float* lng   = (const float*)d_in[9];
    const float* lnb   = (const float*)d_in[10];
    const float* Wo    = (const float*)d_in[11];
    const float* bo    = (const float*)d_in[12];
    float* out = (float*)d_out;

    __half *paq, *pak, *pav, *pq, *pk, *pv, *px;
    __half *pwq, *pwk, *pwv, *pwo;
    cudaGetSymbolAddress((void**)&paq, g_aq);
    cudaGetSymbolAddress((void**)&pak, g_ak);
    cudaGetSymbolAddress((void**)&pav, g_av);
    cudaGetSymbolAddress((void**)&pq,  g_q16);
    cudaGetSymbolAddress((void**)&pk,  g_k16);
    cudaGetSymbolAddress((void**)&pv,  g_v16);
    cudaGetSymbolAddress((void**)&px,  g_x16);
    cudaGetSymbolAddress((void**)&pwq, g_wq);
    cudaGetSymbolAddress((void**)&pwk, g_wk);
    cudaGetSymbolAddress((void**)&pwv, g_wv);
    cudaGetSymbolAddress((void**)&pwo, g_wo);

    cudaFuncSetAttribute(gemm_mma<float>,
                         cudaFuncAttributeMaxDynamicSharedMemorySize, GEMM_SMEM);
    cudaFuncSetAttribute(gemm_qkv,
                         cudaFuncAttributeMaxDynamicSharedMemorySize, GEMM_SMEM);

    conv_all<<<3 * ACT_BLKS + 4 * W_BLKS, 256>>>(
        query, key, value, Wq, Wk, Wv, Wo,
        paq, pak, pav, pwq, pwk, pwv, pwo);

    QKVArgs args;
    args.A[0] = paq; args.A[1] = pak; args.A[2] = pav;
    args.W[0] = pwq; args.W[1] = pwk; args.W[2] = pwv;
    args.bias[0] = bq; args.bias[1] = bk; args.bias[2] = bv;
    args.C[0] = pq; args.C[1] = pk; args.C[2] = pv;
    dim3 gq(DMODEL / 128, M_TOK / 128, 3);
    gemm_qkv<<<gq, 128, GEMM_SMEM>>>(args, DMODEL, DMODEL);

    attn_ln<<<M_TOK, 256>>>(pq, pk, pv, lng, lnb, px);

    dim3 gg(DMODEL / 128, M_TOK / 128);
    gemm_mma<float><<<gg, 128, GEMM_SMEM>>>(px, pwo, bo, out, DMODEL, DMODEL);
}

// round 17
// speedup vs baseline: 1.5385x; 1.0217x over previous
#include <cuda_runtime.h>
#include <cuda_fp16.h>
#include <cstdint>

// ---------------------------------------------------------------------------
// Round 17: R16 GEMMs (frozen) + attn_ln with 2 tokens/block (double MLP)
//           + conv_all with 16 elems/thread (double MLP).
// ---------------------------------------------------------------------------

#define M_TOK   16384
#define DMODEL  1024
#define NTOK_EL (M_TOK * DMODEL)
#define NW_EL   (DMODEL * DMODEL)

__device__ __half g_aq[NTOK_EL];
__device__ __half g_ak[NTOK_EL];
__device__ __half g_av[NTOK_EL];
__device__ __half g_q16[NTOK_EL];
__device__ __half g_k16[NTOK_EL];
__device__ __half g_v16[NTOK_EL];
__device__ __half g_x16[NTOK_EL];
__device__ __half g_wq[NW_EL];
__device__ __half g_wk[NW_EL];
__device__ __half g_wv[NW_EL];
__device__ __half g_wo[NW_EL];

// ---------------- PTX helpers ----------------
__device__ __forceinline__ uint32_t smem_u32(const void* p) {
    return (uint32_t)__cvta_generic_to_shared(p);
}
__device__ __forceinline__ void cp16(uint32_t dst, const void* src) {
    asm volatile("cp.async.cg.shared.global [%0], [%1], 16;"
                 :: "r"(dst), "l"(src) : "memory");
}
__device__ __forceinline__ void cp_commit() {
    asm volatile("cp.async.commit_group;" ::: "memory");
}
__device__ __forceinline__ void cp_wait1() {
    asm volatile("cp.async.wait_group 1;" ::: "memory");
}
__device__ __forceinline__ void ldsm4(uint32_t* r, uint32_t addr) {
    asm volatile("ldmatrix.sync.aligned.m8n8.x4.shared.b16 {%0,%1,%2,%3}, [%4];"
                 : "=r"(r[0]), "=r"(r[1]), "=r"(r[2]), "=r"(r[3]) : "r"(addr));
}
__device__ __forceinline__ void mma16816(float* c, const uint32_t* a, const uint32_t* b) {
    asm volatile(
        "mma.sync.aligned.m16n8k16.row.col.f32.f16.f16.f32 "
        "{%0,%1,%2,%3}, {%4,%5,%6,%7}, {%8,%9}, {%0,%1,%2,%3};"
        : "+f"(c[0]), "+f"(c[1]), "+f"(c[2]), "+f"(c[3])
        : "r"(a[0]), "r"(a[1]), "r"(a[2]), "r"(a[3]), "r"(b[0]), "r"(b[1]));
}

// ---------------- fused convert: 16 elems/thread ----------------
#define ACT_BLKS 4096
#define W_BLKS   256

__global__ __launch_bounds__(256)
void conv_all(const float* __restrict__ a0, const float* __restrict__ a1,
              const float* __restrict__ a2,
              const float* __restrict__ w0, const float* __restrict__ w1,
              const float* __restrict__ w2, const float* __restrict__ w3,
              __half* __restrict__ ya0, __half* __restrict__ ya1,
              __half* __restrict__ ya2,
              __half* __restrict__ yw0, __half* __restrict__ yw1,
              __half* __restrict__ yw2, __half* __restrict__ yw3)
{
    int b = blockIdx.x;
    const float* x; __half* y; int blk;
    if (b < 3 * ACT_BLKS) {
        int t = b / ACT_BLKS;
        x = (t == 0) ? a0 : (t == 1) ? a1 : a2;
        y = (t == 0) ? ya0 : (t == 1) ? ya1 : ya2;
        blk = b - t * ACT_BLKS;
    } else {
        int r = b - 3 * ACT_BLKS;
        int t = r / W_BLKS;
        x = (t == 0) ? w0 : (t == 1) ? w1 : (t == 2) ? w2 : w3;
        y = (t == 0) ? yw0 : (t == 1) ? yw1 : (t == 2) ? yw2 : yw3;
        blk = r - t * W_BLKS;
    }
    int i = (blk * 256 + threadIdx.x) * 16;
    float4 v0 = *(const float4*)(x + i);
    float4 v1 = *(const float4*)(x + i + 4);
    float4 v2 = *(const float4*)(x + i + 8);
    float4 v3 = *(const float4*)(x + i + 12);
    __half2 h[8];
    h[0] = __floats2half2_rn(v0.x, v0.y);
    h[1] = __floats2half2_rn(v0.z, v0.w);
    h[2] = __floats2half2_rn(v1.x, v1.y);
    h[3] = __floats2half2_rn(v1.z, v1.w);
    h[4] = __floats2half2_rn(v2.x, v2.y);
    h[5] = __floats2half2_rn(v2.z, v2.w);
    h[6] = __floats2half2_rn(v3.x, v3.y);
    h[7] = __floats2half2_rn(v3.z, v3.w);
    *(uint4*)(y + i)     = *(uint4*)&h[0];
    *(uint4*)(y + i + 8) = *(uint4*)&h[4];
}

// ---------------- HMMA GEMM core: CTA 128x128, warp 64x64, BK=64 ----------
#define BK          64
#define MAT_BYTES   16384
#define STAGE_BYTES 32768
#define STAGES      3
#define GEMM_SMEM   (STAGES * STAGE_BYTES)

__device__ __forceinline__ void load_stage(const __half* A, const __half* W,
                                           int kb, uint32_t sdst,
                                           int tid, int m0, int n0, int K)
{
    #pragma unroll
    for (int i = 0; i < 16; i++) {
        const int id  = i * 128 + tid;
        const int mat = id >> 10;
        const int idx = id & 1023;
        const int row = idx >> 3;
        const int ch  = idx & 7;
        const int grow = ((mat == 0) ? m0 : n0) + row;
        const __half* src = (mat == 0) ? A : W;
        const void* g = src + (size_t)grow * K + kb * BK + ch * 8;
        const uint32_t d = sdst + mat * MAT_BYTES + row * 128
                         + (((uint32_t)(ch ^ (row & 7))) << 4);
        cp16(d, g);
    }
}

template <typename OutT>
__device__ __forceinline__ void gemm_core(const __half* A, const __half* W,
                                          const float* bias, OutT* C,
                                          int K, int Ntot, int m0, int n0,
                                          char* smem)
{
    const uint32_t sbase = smem_u32(smem);
    const int tid  = threadIdx.x;
    const int lane = tid & 31;
    const int wid  = tid >> 5;
    const int wm   = wid >> 1;
    const int wn   = wid & 1;

    const int g = lane >> 3, j = lane & 7;
    const int cA = g >> 1;
    const int rowA_base = wm * 64 + ((g & 1) ? 8 : 0) + j;
    const int cB = g & 1;
    const int rowB_base = wn * 64 + ((g >> 1) ? 8 : 0) + j;

    float acc[4][8][4];
    #pragma unroll
    for (int a = 0; a < 4; a++)
        #pragma unroll
        for (int b = 0; b < 8; b++)
            #pragma unroll
            for (int c = 0; c < 4; c++) acc[a][b][c] = 0.f;

    uint32_t ar[2][4][4];
    uint32_t bw[2][16];

    auto load_frags = [&](int buf, int k16, uint32_t st) {
        const int c0 = k16 * 2;
        #pragma unroll
        for (int mf = 0; mf < 4; mf++) {
            const int row = rowA_base + mf * 16;
            const uint32_t ad = st + row * 128
                + (((uint32_t)((c0 + cA) ^ (row & 7))) << 4);
            ldsm4(ar[buf][mf], ad);
        }
        #pragma unroll
        for (int p = 0; p < 4; p++) {
            const int row = rowB_base + p * 16;
            const uint32_t bd = st + MAT_BYTES + row * 128
                + (((uint32_t)((c0 + cB) ^ (row & 7))) << 4);
            ldsm4(&bw[buf][p * 4], bd);
        }
    };

    const int nkb = K / BK;
    load_stage(A, W, 0, sbase,               tid, m0, n0, K); cp_commit();
    load_stage(A, W, 1, sbase + STAGE_BYTES, tid, m0, n0, K); cp_commit();

    for (int kb = 0; kb < nkb; kb++) {
        cp_wait1();
        __syncthreads();
        if (kb + 2 < nkb)
            load_stage(A, W, kb + 2, sbase + ((kb + 2) % STAGES) * STAGE_BYTES,
                       tid, m0, n0, K);
        cp_commit();

        const uint32_t st = sbase + (kb % STAGES) * STAGE_BYTES;
        load_frags(0, 0, st);

        #pragma unroll
        for (int k16 = 0; k16 < 4; k16++) {
            const int cur = k16 & 1;
            if (k16 < 3) load_frags(cur ^ 1, k16 + 1, st);
            #pragma unroll
            for (int mf = 0; mf < 4; mf++)
                #pragma unroll
                for (int nf = 0; nf < 8; nf++)
                    mma16816(acc[mf][nf], ar[cur][mf], &bw[cur][nf * 2]);
        }
    }

    const int rl = lane >> 2;
    const int cl = (lane & 3) * 2;
    #pragma unroll
    for (int mf = 0; mf < 4; mf++) {
        const int grow = m0 + wm * 64 + mf * 16 + rl;
        #pragma unroll
        for (int nf = 0; nf < 8; nf++) {
            const int gcol = n0 + wn * 64 + nf * 8 + cl;
            const float2 b2 = __ldg((const float2*)&bias[gcol]);
            float v0 = acc[mf][nf][0] + b2.x, v1 = acc[mf][nf][1] + b2.y;
            float v2 = acc[mf][nf][2] + b2.x, v3 = acc[mf][nf][3] + b2.y;
            if constexpr (sizeof(OutT) == 4) {
                *(float2*)&C[(size_t)grow * Ntot + gcol]       = make_float2(v0, v1);
                *(float2*)&C[(size_t)(grow + 8) * Ntot + gcol] = make_float2(v2, v3);
            } else {
                *(__half2*)&C[(size_t)grow * Ntot + gcol]       = __floats2half2_rn(v0, v1);
                *(__half2*)&C[(size_t)(grow + 8) * Ntot + gcol] = __floats2half2_rn(v2, v3);
            }
        }
    }
}

template <typename OutT>
__global__ __launch_bounds__(128, 2)
void gemm_mma(const __half* __restrict__ A, const __half* __restrict__ W,
              const float* __restrict__ bias, OutT* __restrict__ C,
              int K, int Ntot)
{
    extern __shared__ char smem[];
    gemm_core<OutT>(A, W, bias, C, K, Ntot,
                    blockIdx.y * 128, blockIdx.x * 128, smem);
}

struct QKVArgs {
    const __half* A[3];
    const __half* W[3];
    const float*  bias[3];
    __half*       C[3];
};

__global__ __launch_bounds__(128, 2)
void gemm_qkv(QKVArgs args, int K, int Ntot)
{
    extern __shared__ char smem[];
    const int z = blockIdx.z;
    gemm_core<__half>(args.A[z], args.W[z], args.bias[z], args.C[z], K, Ntot,
                      blockIdx.y * 128, blockIdx.x * 128, smem);
}

// ---------------- attn+LN: 2 tokens per 256-thread block -------------------
// All 6 global loads issued before the single sync (MLP=6); per-token math
// and summation order identical to the 1-token version (bit-identical out).
__global__ __launch_bounds__(256)
void attn_ln2(const __half* __restrict__ Q, const __half* __restrict__ Kp,
              const __half* __restrict__ V, const float* __restrict__ lng,
              const float* __restrict__ lnb, __half* __restrict__ X)
{
    __shared__ float4 sq4[2][256];
    __shared__ float4 sv4[2][256];
    __shared__ float4 sk4[2][16 * 17];
    __shared__ float  rbuf[2][2][8];   // [tok][stat][warp]

    const int tid = threadIdx.x;
    const int h  = tid >> 4;
    const int d4 = tid & 15;
    const size_t base0 = (size_t)(blockIdx.x * 2) * 1024;
    const size_t base1 = base0 + 1024;

    auto ld4h = [&](const __half* p, size_t base) -> float4 {
        uint2 u = *(const uint2*)(p + base + tid * 4);
        float2 a = __half22float2(*(__half2*)&u.x);
        float2 b = __half22float2(*(__half2*)&u.y);
        return make_float4(a.x, a.y, b.x, b.y);
    };
    // issue all 6 loads (compiler batches the LDG.64s -> deep MLP)
    sq4[0][tid] = ld4h(Q,  base0);
    sv4[0][tid] = ld4h(V,  base0);
    sk4[0][h * 17 + d4] = ld4h(Kp, base0);
    sq4[1][tid] = ld4h(Q,  base1);
    sv4[1][tid] = ld4h(V,  base1);
    sk4[1][h * 17 + d4] = ld4h(Kp, base1);
    __syncthreads();

    float4 o[2];
    float s1[2], s2[2];
    #pragma unroll
    for (int t = 0; t < 2; t++) {
        float e = 0.f;
        {
            const int gg = d4;
            #pragma unroll
            for (int q4i = 0; q4i < 16; q4i++) {
                float4 a = sq4[t][h * 16 + q4i];
                float4 b = sk4[t][gg * 17 + q4i];
                e += a.x * b.x + a.y * b.y + a.z * b.z + a.w * b.w;
            }
            e *= 0.03125f;   // 1/sqrt(1024)
        }
        float mx = e;
        #pragma unroll
        for (int off = 8; off > 0; off >>= 1)
            mx = fmaxf(mx, __shfl_xor_sync(0xffffffffu, mx, off, 16));
        float p = __expf(e - mx);
        float s = p;
        #pragma unroll
        for (int off = 8; off > 0; off >>= 1)
            s += __shfl_xor_sync(0xffffffffu, s, off, 16);
        const float attn = p / s;

        float4 acc = make_float4(0.f, 0.f, 0.f, 0.f);
        #pragma unroll
        for (int gg = 0; gg < 16; gg++) {
            const float w = __shfl_sync(0xffffffffu, attn, gg, 16);
            const float4 vv = sv4[t][gg * 16 + d4];
            acc.x += w * vv.x; acc.y += w * vv.y;
            acc.z += w * vv.z; acc.w += w * vv.w;
        }
        o[t] = acc;
        float a1 = acc.x + acc.y + acc.z + acc.w;
        float a2 = acc.x * acc.x + acc.y * acc.y + acc.z * acc.z + acc.w * acc.w;
        #pragma unroll
        for (int off = 16; off > 0; off >>= 1) {
            a1 += __shfl_xor_sync(0xffffffffu, a1, off);
            a2 += __shfl_xor_sync(0xffffffffu, a2, off);
        }
        s1[t] = a1; s2[t] = a2;
    }

    const int wid = tid >> 5, lane = tid & 31;
    if (lane == 0) {
        rbuf[0][0][wid] = s1[0]; rbuf[0][1][wid] = s2[0];
        rbuf[1][0][wid] = s1[1]; rbuf[1][1][wid] = s2[1];
    }
    __syncthreads();
    if (tid < 2) {
        float t1 = 0.f, t2 = 0.f;
        #pragma unroll
        for (int w = 0; w < 8; w++) { t1 += rbuf[tid][0][w]; t2 += rbuf[tid][1][w]; }
        float mu  = t1 * (1.f / 1024.f);
        float var = t2 * (1.f / 1024.f) - mu * mu;
        rbuf[tid][0][0] = mu;
        rbuf[tid][1][0] = rsqrtf(var + 1e-5f);
    }
    __syncthreads();

    const float4 gam = *(const float4*)&lng[tid * 4];
    const float4 bet = *(const float4*)&lnb[tid * 4];
    #pragma unroll
    for (int t = 0; t < 2; t++) {
        const float mu = rbuf[t][0][0], rstd = rbuf[t][1][0];
        float4 r;
        r.x = (o[t].x - mu) * rstd * gam.x + bet.x;
        r.y = (o[t].y - mu) * rstd * gam.y + bet.y;
        r.z = (o[t].z - mu) * rstd * gam.z + bet.z;
        r.w = (o[t].w - mu) * rstd * gam.w + bet.w;
        __half2 h01 = __floats2half2_rn(r.x, r.y);
        __half2 h23 = __floats2half2_rn(r.z, r.w);
        uint2 pk;
        pk.x = *(uint32_t*)&h01;
        pk.y = *(uint32_t*)&h23;
        *(uint2*)&X[(t == 0 ? base0 : base1) + tid * 4] = pk;
    }
}

// ---------------- launch ----------------
extern "C" void kernel_launch(void* const* d_in, const int* in_sizes, int n_in,
                              void* d_out, int out_size)
{
    const float* query = (const float*)d_in[0];
    const float* key   = (const float*)d_in[1];
    const float* value = (const float*)d_in[2];
    const float* Wq    = (const float*)d_in[3];
    const float* bq    = (const float*)d_in[4];
    const float* Wk    = (const float*)d_in[5];
    const float* bk    = (const float*)d_in[6];
    const float* Wv    = (const float*)d_in[7];
    const float* bv    = (const float*)d_in[8];
    const float* lng   = (const float*)d_in[9];
    const float* lnb   = (const float*)d_in[10];
    const float* Wo    = (const float*)d_in[11];
    const float* bo    = (const float*)d_in[12];
    float* out = (float*)d_out;

    __half *paq, *pak, *pav, *pq, *pk, *pv, *px;
    __half *pwq, *pwk, *pwv, *pwo;
    cudaGetSymbolAddress((void**)&paq, g_aq);
    cudaGetSymbolAddress((void**)&pak, g_ak);
    cudaGetSymbolAddress((void**)&pav, g_av);
    cudaGetSymbolAddress((void**)&pq,  g_q16);
    cudaGetSymbolAddress((void**)&pk,  g_k16);
    cudaGetSymbolAddress((void**)&pv,  g_v16);
    cudaGetSymbolAddress((void**)&px,  g_x16);
    cudaGetSymbolAddress((void**)&pwq, g_wq);
    cudaGetSymbolAddress((void**)&pwk, g_wk);
    cudaGetSymbolAddress((void**)&pwv, g_wv);
    cudaGetSymbolAddress((void**)&pwo, g_wo);

    cudaFuncSetAttribute(gemm_mma<float>,
                         cudaFuncAttributeMaxDynamicSharedMemorySize, GEMM_SMEM);
    cudaFuncSetAttribute(gemm_qkv,
                         cudaFuncAttributeMaxDynamicSharedMemorySize, GEMM_SMEM);

    conv_all<<<3 * ACT_BLKS + 4 * W_BLKS, 256>>>(
        query, key, value, Wq, Wk, Wv, Wo,
        paq, pak, pav, pwq, pwk, pwv, pwo);

    QKVArgs args;
    args.A[0] = paq; args.A[1] = pak; args.A[2] = pav;
    args.W[0] = pwq; args.W[1] = pwk; args.W[2] = pwv;
    args.bias[0] = bq; args.bias[1] = bk; args.bias[2] = bv;
    args.C[0] = pq; args.C[1] = pk; args.C[2] = pv;
    dim3 gq(DMODEL / 128, M_TOK / 128, 3);
    gemm_qkv<<<gq, 128, GEMM_SMEM>>>(args, DMODEL, DMODEL);

    attn_ln2<<<M_TOK / 2, 256>>>(pq, pk, pv, lng, lnb, px);

    dim3 gg(DMODEL / 128, M_TOK / 128);
    gemm_mma<float><<<gg, 128, GEMM_SMEM>>>(px, pwo, bo, out, DMODEL, DMODEL);
}